// round 10
// baseline (speedup 1.0000x reference)
#include <cuda_runtime.h>

#define LATENTS 128
#define HIDDEN  256
#define TM      32
#define NTHR    512
#define TSTEPS  100
#define NROWS   4096

typedef unsigned long long ULL;
typedef ulonglong2 U2;

// k-pair-packed weights, built once per launch.
__device__ float W1p_g[64 * 256 * 2];    // ULL view [64][256]: (W1[2j][c], W1[2j+1][c])
__device__ float W2p_g[128 * 128 * 2];   // ULL view [128][128]: (W2[2j][c], W2[2j+1][c])

__device__ __forceinline__ ULL ffma2(ULL a, ULL b, ULL c) {
    ULL d; asm("fma.rn.f32x2 %0, %1, %2, %3;" : "=l"(d) : "l"(a), "l"(b), "l"(c)); return d;
}
__device__ __forceinline__ ULL add2(ULL a, ULL b) {
    ULL d; asm("add.rn.f32x2 %0, %1, %2;" : "=l"(d) : "l"(a), "l"(b)); return d;
}
__device__ __forceinline__ ULL packab(float a, float b) {
    ULL d; asm("mov.b64 %0, {%1, %2};" : "=l"(d) : "f"(a), "f"(b)); return d;
}
__device__ __forceinline__ float hadd2(ULL v) {
    float lo, hi; asm("mov.b64 {%0, %1}, %2;" : "=f"(lo), "=f"(hi) : "l"(v));
    return lo + hi;
}
__device__ __forceinline__ float fast_tanh(float x) {
    float e = __expf(2.0f * x);
    return 1.0f - __fdividef(2.0f, e + 1.0f);
}
__device__ __forceinline__ void cp16(unsigned dst, const float* src) {
    asm volatile("cp.async.cg.shared.global [%0], [%1], 16;" :: "r"(dst), "l"(src) : "memory");
}
__device__ __forceinline__ void cp_commit() {
    asm volatile("cp.async.commit_group;" ::: "memory");
}
__device__ __forceinline__ void cp_wait1() {
    asm volatile("cp.async.wait_group 1;" ::: "memory");
}

__global__ void pack_weights_kernel(const float* __restrict__ W1,
                                    const float* __restrict__ W2) {
    int i = blockIdx.x * blockDim.x + threadIdx.x;   // 16384 threads
    int j1 = i >> 8, c1 = i & 255;
    ((float2*)W1p_g)[i] = make_float2(W1[(2 * j1) * HIDDEN + c1],
                                      W1[(2 * j1 + 1) * HIDDEN + c1]);
    int j2 = i >> 7, c2 = i & 127;
    ((float2*)W2p_g)[i] = make_float2(W2[(2 * j2) * LATENTS + c2],
                                      W2[(2 * j2 + 1) * LATENTS + c2]);
}

// smem (bytes): W1s [0,131072)       ULL[64][256]   k-pair W1
//               Ykp [131072,147456)  U2 [16][64]    (row-pair x k-pair) state
//               Zkp [147456,180224)  U2 [16][128]   (row-pair x hj-pair) acts
//               W2t [180224,229376)  3 x 16KB tile bufs (ULL[16][128] each)
//               Red = bufs 0+1 (32KB), used only after all tiles consumed
#define SM_BYTES 229376

__global__ __launch_bounds__(NTHR, 1)
void ode_rk4_kernel(const float* __restrict__ fp,
                    const float* __restrict__ ts,
                    const float* __restrict__ b1,
                    const float* __restrict__ b2,
                    float* __restrict__ out)
{
    extern __shared__ char smraw[];
    ULL*   W1s = (ULL*)smraw;
    U2*    Ykp = (U2*)(smraw + 131072);
    U2*    Zkp = (U2*)(smraw + 147456);
    float* W2t = (float*)(smraw + 180224);
    ULL*   Red = (ULL*)(smraw + 180224);

    const int tid = threadIdx.x;
    const int tc  = tid & 31;
    const int w   = tid >> 5;
    // GEMM1 tile: pairs 4wr..4wr+3, cols (c1, c1+1)
    const int wr  = w >> 2;
    const int wc  = w & 3;
    const int c1  = 64 * wc + 2 * tc;
    const int hj1 = 32 * wc + tc;          // c1/2: hidden j-pair index
    // GEMM2 tile: pairs 4rg..4rg+3, cols (c2, c2+1), k-half gr
    const int rg  = (w & 7) >> 1;
    const int wc2 = w & 1;
    const int c2  = 64 * wc2 + 2 * tc;
    const int kj2 = 32 * wc2 + tc;         // c2/2: latent j-pair index
    const int gr  = w >> 3;
    const bool epi_w = (w < 8);
    const int row0 = blockIdx.x * TM;

    unsigned smem_base;
    asm("{ .reg .u64 t; cvta.to.shared.u64 t, %1; cvt.u32.u64 %0, t; }"
        : "=r"(smem_base) : "l"(smraw));
    const unsigned W2t_u = smem_base + 180224;

    // Stage k-pair W1 into smem (coalesced float4).
    for (int i = tid; i < 131072 / 16; i += NTHR)
        ((float4*)W1s)[i] = ((const float4*)W1p_g)[i];

    // t=0 output, fully coalesced.
    for (int i = tid; i < TM * LATENTS / 4; i += NTHR) {
        int r = i >> 5, c4 = i & 31;
        float4 v = ((const float4*)(fp + (size_t)(row0 + r) * LATENTS))[c4];
        ((float4*)(out + (size_t)(row0 + r) * TSTEPS * LATENTS))[c4] = v;
    }

    const ULL rb1a = packab(b1[c1], 0.f);
    const ULL rb1b = packab(b1[c1 + 1], 0.f);

    float yb[4][2][2], acc[4][2][2];
    ULL rb2a = 0, rb2b = 0;
    if (epi_w) {
        rb2a = packab(b2[c2], 0.f);
        rb2b = packab(b2[c2 + 1], 0.f);
        #pragma unroll
        for (int p = 0; p < 4; p++) {
            int r = row0 + 8 * rg + 2 * p;
            yb[p][0][0] = fp[(size_t)r * LATENTS + c2];
            yb[p][0][1] = fp[(size_t)r * LATENTS + c2 + 1];
            yb[p][1][0] = fp[(size_t)(r + 1) * LATENTS + c2];
            yb[p][1][1] = fp[(size_t)(r + 1) * LATENTS + c2 + 1];
            U2 yy;
            yy.x = packab(yb[p][0][0], yb[p][0][1]);
            yy.y = packab(yb[p][1][0], yb[p][1][1]);
            Ykp[(4 * rg + p) * 64 + kj2] = yy;
        }
    }
    __syncthreads();

    for (int t = 0; t < TSTEPS - 1; t++) {
        float dt   = __ldg(&ts[t + 1]) - __ldg(&ts[t]);
        float half = 0.5f * dt;

        #pragma unroll 1
        for (int s = 0; s < 4; s++) {
            // All threads: async-commit tiles 0 and 1 (land during GEMM1).
            {
                const float* s0 = (const float*)W2p_g + tid * 8;
                unsigned d0 = W2t_u + (unsigned)tid * 32;
                cp16(d0, s0); cp16(d0 + 16, s0 + 4);
                cp_commit();
                const float* s1 = s0 + 4096;
                unsigned d1 = d0 + 16384;
                cp16(d1, s1); cp16(d1 + 16, s1 + 4);
                cp_commit();
            }

            // ------- GEMM1: 4 row-pairs x 2 cols, all operands pre-paired ---
            ULL h[4][2][2];
            #pragma unroll
            for (int p = 0; p < 4; p++) {
                h[p][0][0] = rb1a; h[p][0][1] = rb1b;
                h[p][1][0] = rb1a; h[p][1][1] = rb1b;
            }
            {
                const ULL* w1 = W1s + c1;
                const U2*  yp = Ykp + (4 * wr) * 64;
                #pragma unroll 2
                for (int j = 0; j < 64; j++) {
                    U2 wv = *(const U2*)&w1[j * 256];
                    U2 y0 = yp[j];
                    U2 y1 = yp[64 + j];
                    U2 y2 = yp[128 + j];
                    U2 y3 = yp[192 + j];
                    h[0][0][0] = ffma2(y0.x, wv.x, h[0][0][0]); h[0][0][1] = ffma2(y0.x, wv.y, h[0][0][1]);
                    h[0][1][0] = ffma2(y0.y, wv.x, h[0][1][0]); h[0][1][1] = ffma2(y0.y, wv.y, h[0][1][1]);
                    h[1][0][0] = ffma2(y1.x, wv.x, h[1][0][0]); h[1][0][1] = ffma2(y1.x, wv.y, h[1][0][1]);
                    h[1][1][0] = ffma2(y1.y, wv.x, h[1][1][0]); h[1][1][1] = ffma2(y1.y, wv.y, h[1][1][1]);
                    h[2][0][0] = ffma2(y2.x, wv.x, h[2][0][0]); h[2][0][1] = ffma2(y2.x, wv.y, h[2][0][1]);
                    h[2][1][0] = ffma2(y2.y, wv.x, h[2][1][0]); h[2][1][1] = ffma2(y2.y, wv.y, h[2][1][1]);
                    h[3][0][0] = ffma2(y3.x, wv.x, h[3][0][0]); h[3][0][1] = ffma2(y3.x, wv.y, h[3][0][1]);
                    h[3][1][0] = ffma2(y3.y, wv.x, h[3][1][0]); h[3][1][1] = ffma2(y3.y, wv.y, h[3][1][1]);
                }
            }

            // hadd + tanh -> Zkp (pairs re-packed; STS.128 dense, conflict-free)
            #pragma unroll
            for (int p = 0; p < 4; p++) {
                U2 zz;
                zz.x = packab(fast_tanh(hadd2(h[p][0][0])), fast_tanh(hadd2(h[p][0][1])));
                zz.y = packab(fast_tanh(hadd2(h[p][1][0])), fast_tanh(hadd2(h[p][1][1])));
                Zkp[(4 * wr + p) * 128 + hj1] = zz;
            }
            __syncthreads();

            // ------- GEMM2: all 16 warps; partners (w, w+8) split j of tile -
            ULL o[4][2][2];
            if (gr == 0) {
                #pragma unroll
                for (int p = 0; p < 4; p++) {
                    o[p][0][0] = rb2a; o[p][0][1] = rb2b;
                    o[p][1][0] = rb2a; o[p][1][1] = rb2b;
                }
            } else {
                #pragma unroll
                for (int p = 0; p < 4; p++) {
                    o[p][0][0] = 0ULL; o[p][0][1] = 0ULL;
                    o[p][1][0] = 0ULL; o[p][1][1] = 0ULL;
                }
            }

            #pragma unroll 1
            for (int kt = 0; kt < 8; kt++) {
                cp_wait1();
                __syncthreads();
                if (kt < 6) {
                    const float* src = (const float*)W2p_g + (kt + 2) * 4096 + tid * 8;
                    unsigned dst = W2t_u + (unsigned)(((kt + 2) % 3) * 16384 + tid * 32);
                    cp16(dst, src); cp16(dst + 16, src + 4);
                    cp_commit();
                }
                {
                    const ULL* Wt = (const ULL*)(W2t + (kt % 3) * 4096);
                    const U2*  zp = Zkp + (4 * rg) * 128;
                    const int  jb = 16 * kt + 8 * gr;
                    #pragma unroll 2
                    for (int jl = 0; jl < 8; jl++) {
                        const int jg = jb + jl;
                        U2 wv = *(const U2*)&Wt[(8 * gr + jl) * 128 + c2];
                        U2 z0 = zp[jg];
                        U2 z1 = zp[128 + jg];
                        U2 z2 = zp[256 + jg];
                        U2 z3 = zp[384 + jg];
                        o[0][0][0] = ffma2(z0.x, wv.x, o[0][0][0]); o[0][0][1] = ffma2(z0.x, wv.y, o[0][0][1]);
                        o[0][1][0] = ffma2(z0.y, wv.x, o[0][1][0]); o[0][1][1] = ffma2(z0.y, wv.y, o[0][1][1]);
                        o[1][0][0] = ffma2(z1.x, wv.x, o[1][0][0]); o[1][0][1] = ffma2(z1.x, wv.y, o[1][0][1]);
                        o[1][1][0] = ffma2(z1.y, wv.x, o[1][1][0]); o[1][1][1] = ffma2(z1.y, wv.y, o[1][1][1]);
                        o[2][0][0] = ffma2(z2.x, wv.x, o[2][0][0]); o[2][0][1] = ffma2(z2.x, wv.y, o[2][0][1]);
                        o[2][1][0] = ffma2(z2.y, wv.x, o[2][1][0]); o[2][1][1] = ffma2(z2.y, wv.y, o[2][1][1]);
                        o[3][0][0] = ffma2(z3.x, wv.x, o[3][0][0]); o[3][0][1] = ffma2(z3.x, wv.y, o[3][0][1]);
                        o[3][1][0] = ffma2(z3.y, wv.x, o[3][1][0]); o[3][1][1] = ffma2(z3.y, wv.y, o[3][1][1]);
                    }
                }
            }

            // ------- partner reduction: group1 -> smem (bufs 0+1), group0 adds
            __syncthreads();                       // all tiles consumed
            if (gr == 1) {
                ULL* rd = &Red[((w - 8) * 32 + tc) * 16];
                #pragma unroll
                for (int p = 0; p < 4; p++) {
                    U2 a; a.x = o[p][0][0]; a.y = o[p][0][1];
                    U2 b; b.x = o[p][1][0]; b.y = o[p][1][1];
                    *(U2*)&rd[4 * p]     = a;
                    *(U2*)&rd[4 * p + 2] = b;
                }
            }
            __syncthreads();
            if (gr == 0) {
                const ULL* rd = &Red[(w * 32 + tc) * 16];
                #pragma unroll
                for (int p = 0; p < 4; p++) {
                    U2 a = *(const U2*)&rd[4 * p];
                    U2 b = *(const U2*)&rd[4 * p + 2];
                    o[p][0][0] = add2(o[p][0][0], a.x);
                    o[p][0][1] = add2(o[p][0][1], a.y);
                    o[p][1][0] = add2(o[p][1][0], b.x);
                    o[p][1][1] = add2(o[p][1][1], b.y);
                }
            }

            // ------- RK4 epilogue (scalar, warps 0-7) -----------------------
            if (epi_w) {
                float of[4][2][2];
                #pragma unroll
                for (int p = 0; p < 4; p++) {
                    of[p][0][0] = hadd2(o[p][0][0]); of[p][0][1] = hadd2(o[p][0][1]);
                    of[p][1][0] = hadd2(o[p][1][0]); of[p][1][1] = hadd2(o[p][1][1]);
                }
                if (s == 0) {
                    #pragma unroll
                    for (int p = 0; p < 4; p++)
                        #pragma unroll
                        for (int e = 0; e < 2; e++) {
                            acc[p][e][0] = of[p][e][0];
                            acc[p][e][1] = of[p][e][1];
                        }
                } else {
                    float cw = (s == 3) ? 1.0f : 2.0f;
                    #pragma unroll
                    for (int p = 0; p < 4; p++)
                        #pragma unroll
                        for (int e = 0; e < 2; e++) {
                            acc[p][e][0] = fmaf(cw, of[p][e][0], acc[p][e][0]);
                            acc[p][e][1] = fmaf(cw, of[p][e][1], acc[p][e][1]);
                        }
                }
                if (s < 3) {
                    float ew = (s < 2) ? half : dt;
                    #pragma unroll
                    for (int p = 0; p < 4; p++) {
                        U2 yy;
                        yy.x = packab(fmaf(ew, of[p][0][0], yb[p][0][0]),
                                      fmaf(ew, of[p][0][1], yb[p][0][1]));
                        yy.y = packab(fmaf(ew, of[p][1][0], yb[p][1][0]),
                                      fmaf(ew, of[p][1][1], yb[p][1][1]));
                        Ykp[(4 * rg + p) * 64 + kj2] = yy;
                    }
                } else {
                    float c6 = dt * (1.0f / 6.0f);
                    #pragma unroll
                    for (int p = 0; p < 4; p++) {
                        #pragma unroll
                        for (int e = 0; e < 2; e++) {
                            yb[p][e][0] = fmaf(c6, acc[p][e][0], yb[p][e][0]);
                            yb[p][e][1] = fmaf(c6, acc[p][e][1], yb[p][e][1]);
                        }
                        U2 yy;
                        yy.x = packab(yb[p][0][0], yb[p][0][1]);
                        yy.y = packab(yb[p][1][0], yb[p][1][1]);
                        Ykp[(4 * rg + p) * 64 + kj2] = yy;
                        int r = row0 + 8 * rg + 2 * p;
                        float2 v0; v0.x = yb[p][0][0]; v0.y = yb[p][0][1];
                        float2 v1; v1.x = yb[p][1][0]; v1.y = yb[p][1][1];
                        *(float2*)&out[((size_t)r * TSTEPS + (t + 1)) * LATENTS + c2] = v0;
                        *(float2*)&out[((size_t)(r + 1) * TSTEPS + (t + 1)) * LATENTS + c2] = v1;
                    }
                }
            }
            __syncthreads();
        }
    }
}

extern "C" void kernel_launch(void* const* d_in, const int* in_sizes, int n_in,
                              void* d_out, int out_size) {
    const float* fp = (const float*)d_in[0];
    const float* ts = (const float*)d_in[1];
    const float* W1 = (const float*)d_in[2];
    const float* b1 = (const float*)d_in[3];
    const float* W2 = (const float*)d_in[4];
    const float* b2 = (const float*)d_in[5];
    float* out = (float*)d_out;

    pack_weights_kernel<<<64, 256>>>(W1, W2);

    cudaFuncSetAttribute(ode_rk4_kernel,
                         cudaFuncAttributeMaxDynamicSharedMemorySize, SM_BYTES);
    ode_rk4_kernel<<<NROWS / TM, NTHR, SM_BYTES>>>(fp, ts, b1, b2, out);
}

// round 12
// speedup vs baseline: 1.3494x; 1.3494x over previous
#include <cuda_runtime.h>

#define LATENTS 128
#define HIDDEN  256
#define TM      32
#define NTHR    512
#define TSTEPS  100
#define NROWS   4096

typedef unsigned long long ULL;

__device__ __forceinline__ ULL ffma2(ULL a, ULL b, ULL c) {
    ULL d; asm("fma.rn.f32x2 %0, %1, %2, %3;" : "=l"(d) : "l"(a), "l"(b), "l"(c)); return d;
}
__device__ __forceinline__ ULL pack2(float x) {
    ULL d; asm("mov.b64 %0, {%1, %1};" : "=l"(d) : "f"(x)); return d;
}
__device__ __forceinline__ ULL packab(float a, float b) {
    ULL d; asm("mov.b64 %0, {%1, %2};" : "=l"(d) : "f"(a), "f"(b)); return d;
}
__device__ __forceinline__ void unpack2(ULL v, float& lo, float& hi) {
    asm("mov.b64 {%0, %1}, %2;" : "=f"(lo), "=f"(hi) : "l"(v));
}
__device__ __forceinline__ float fast_tanh(float x) {
    float e = __expf(2.0f * x);
    return 1.0f - __fdividef(2.0f, e + 1.0f);
}

// smem (bytes): W1s [0,131072)       fp32[128][256]
//               Yp  [131072,147456)  ULL [16][128]   row-pair state
//               Zp  [147456,180224)  ULL [16][256]   row-pair tanh acts
//               Red [180224,196608)  16KB partner-reduction buffer
#define SM_BYTES 196608

__global__ __launch_bounds__(NTHR, 1)
void ode_rk4_kernel(const float* __restrict__ fp,
                    const float* __restrict__ ts,
                    const float* __restrict__ W1,
                    const float* __restrict__ b1,
                    const float* __restrict__ W2,
                    const float* __restrict__ b2,
                    float* __restrict__ out)
{
    extern __shared__ char smraw[];
    float* W1s = (float*)smraw;
    ULL*   Yp  = (ULL*)(smraw + 131072);
    ULL*   Zp  = (ULL*)(smraw + 147456);
    ULL*   Red = (ULL*)(smraw + 180224);

    const int tid = threadIdx.x;
    const int tc  = tid & 31;
    const int w   = tid >> 5;
    const int wr  = w >> 2;          // GEMM1 row group: pairs 4wr..4wr+3
    const int wc  = w & 3;           // GEMM1 col block: 64wc
    const int rg  = (w & 7) >> 1;    // GEMM2 row tile: pairs 4rg..4rg+3
    const int wc2 = w & 1;           // GEMM2 col block: 64wc2
    const int gr  = w >> 3;          // GEMM2 k-half: ks [128gr, 128gr+128)
    const bool epi_w = (w < 8);
    const int row0 = blockIdx.x * TM;

    // Stage W1 (coalesced float4).
    for (int i = tid; i < LATENTS * HIDDEN / 4; i += NTHR)
        ((float4*)W1s)[i] = ((const float4*)W1)[i];

    // t=0 output, fully coalesced.
    for (int i = tid; i < TM * LATENTS / 4; i += NTHR) {
        int r = i >> 5, c4 = i & 31;
        float4 v = ((const float4*)(fp + (size_t)(row0 + r) * LATENTS))[c4];
        ((float4*)(out + (size_t)(row0 + r) * TSTEPS * LATENTS))[c4] = v;
    }

    const ULL rb1lo = pack2(b1[64 * wc + 2 * tc]);
    const ULL rb1hi = pack2(b1[64 * wc + 2 * tc + 1]);

    ULL yb[4][2], acc[4][2], rb2[2];
    const int cb = 64 * wc2 + 2 * tc;
    rb2[0] = pack2(b2[cb]);
    rb2[1] = pack2(b2[cb + 1]);
    if (epi_w) {
        #pragma unroll
        for (int p = 0; p < 4; p++) {
            int r = row0 + 8 * rg + 2 * p;
            yb[p][0] = packab(fp[(size_t)r * LATENTS + cb],     fp[(size_t)(r + 1) * LATENTS + cb]);
            yb[p][1] = packab(fp[(size_t)r * LATENTS + cb + 1], fp[(size_t)(r + 1) * LATENTS + cb + 1]);
            ulonglong2 yy; yy.x = yb[p][0]; yy.y = yb[p][1];
            *(ulonglong2*)&Yp[(4 * rg + p) * LATENTS + cb] = yy;
        }
    }
    __syncthreads();

    for (int t = 0; t < TSTEPS - 1; t++) {
        float dt   = __ldg(&ts[t + 1]) - __ldg(&ts[t]);
        float half = 0.5f * dt;

        #pragma unroll 1
        for (int s = 0; s < 4; s++) {
            // ---------------- GEMM1 (all 16 warps, row-pair) ----------------
            ULL h[4][2];
            #pragma unroll
            for (int p = 0; p < 4; p++) { h[p][0] = rb1lo; h[p][1] = rb1hi; }
            {
                const float* w1c = &W1s[64 * wc + 2 * tc];
                const ULL*   yp0 = &Yp[(4 * wr + 0) * LATENTS];
                const ULL*   yp1 = &Yp[(4 * wr + 1) * LATENTS];
                const ULL*   yp2 = &Yp[(4 * wr + 2) * LATENTS];
                const ULL*   yp3 = &Yp[(4 * wr + 3) * LATENTS];
                #pragma unroll 2
                for (int k0 = 0; k0 < LATENTS; k0 += 2) {
                    ulonglong2 a0 = *(const ulonglong2*)&yp0[k0];
                    ulonglong2 a1 = *(const ulonglong2*)&yp1[k0];
                    ulonglong2 a2 = *(const ulonglong2*)&yp2[k0];
                    ulonglong2 a3 = *(const ulonglong2*)&yp3[k0];
                    ULL wv0 = *(const ULL*)&w1c[(k0    ) * HIDDEN];
                    ULL wv1 = *(const ULL*)&w1c[(k0 + 1) * HIDDEN];
                    float wl, wh;
                    unpack2(wv0, wl, wh);
                    { ULL bl = pack2(wl), bh = pack2(wh);
                      h[0][0] = ffma2(a0.x, bl, h[0][0]); h[0][1] = ffma2(a0.x, bh, h[0][1]);
                      h[1][0] = ffma2(a1.x, bl, h[1][0]); h[1][1] = ffma2(a1.x, bh, h[1][1]);
                      h[2][0] = ffma2(a2.x, bl, h[2][0]); h[2][1] = ffma2(a2.x, bh, h[2][1]);
                      h[3][0] = ffma2(a3.x, bl, h[3][0]); h[3][1] = ffma2(a3.x, bh, h[3][1]); }
                    unpack2(wv1, wl, wh);
                    { ULL bl = pack2(wl), bh = pack2(wh);
                      h[0][0] = ffma2(a0.y, bl, h[0][0]); h[0][1] = ffma2(a0.y, bh, h[0][1]);
                      h[1][0] = ffma2(a1.y, bl, h[1][0]); h[1][1] = ffma2(a1.y, bh, h[1][1]);
                      h[2][0] = ffma2(a2.y, bl, h[2][0]); h[2][1] = ffma2(a2.y, bh, h[2][1]);
                      h[3][0] = ffma2(a3.y, bl, h[3][0]); h[3][1] = ffma2(a3.y, bh, h[3][1]); }
                }
            }

            // tanh -> Zp (dense STS.128, conflict-free).
            #pragma unroll
            for (int p = 0; p < 4; p++) {
                float x0, x1, x2, x3;
                unpack2(h[p][0], x0, x1);
                unpack2(h[p][1], x2, x3);
                ulonglong2 zz;
                zz.x = packab(fast_tanh(x0), fast_tanh(x1));
                zz.y = packab(fast_tanh(x2), fast_tanh(x3));
                *(ulonglong2*)&Zp[(4 * wr + p) * HIDDEN + 64 * wc + 2 * tc] = zz;
            }
            __syncthreads();

            // ------- GEMM2: all 16 warps; W2 streamed via LDG (L2-resident) -
            // Warp covers ks [128gr, 128gr+128), rows 8rg..8rg+7, cols cb,cb+1.
            ULL o[4][2];
            if (gr == 0) {
                #pragma unroll
                for (int p = 0; p < 4; p++) { o[p][0] = rb2[0]; o[p][1] = rb2[1]; }
            } else {
                #pragma unroll
                for (int p = 0; p < 4; p++) { o[p][0] = 0ULL; o[p][1] = 0ULL; }
            }

            {
                const ULL* zb0 = &Zp[(4 * rg + 0) * HIDDEN + 128 * gr];
                const ULL* zb1 = &Zp[(4 * rg + 1) * HIDDEN + 128 * gr];
                const ULL* zb2 = &Zp[(4 * rg + 2) * HIDDEN + 128 * gr];
                const ULL* zb3 = &Zp[(4 * rg + 3) * HIDDEN + 128 * gr];
                const float* Wg = W2 + (size_t)(128 * gr) * LATENTS + cb;

                ULL wbuf[2][8];
                #pragma unroll
                for (int q = 0; q < 8; q++)
                    wbuf[0][q] = *(const ULL*)&Wg[q * LATENTS];

                #pragma unroll 2
                for (int c = 0; c < 16; c++) {
                    if (c < 15) {
                        #pragma unroll
                        for (int q = 0; q < 8; q++)
                            wbuf[(c + 1) & 1][q] = *(const ULL*)&Wg[(8 * (c + 1) + q) * LATENTS];
                    }
                    #pragma unroll
                    for (int q = 0; q < 8; q += 2) {
                        const int kk = 8 * c + q;
                        ulonglong2 a0 = *(const ulonglong2*)&zb0[kk];
                        ulonglong2 a1 = *(const ulonglong2*)&zb1[kk];
                        ulonglong2 a2 = *(const ulonglong2*)&zb2[kk];
                        ulonglong2 a3 = *(const ulonglong2*)&zb3[kk];
                        ULL wv0 = wbuf[c & 1][q];
                        ULL wv1 = wbuf[c & 1][q + 1];
                        float wl, wh;
                        unpack2(wv0, wl, wh);
                        { ULL bl = pack2(wl), bh = pack2(wh);
                          o[0][0] = ffma2(a0.x, bl, o[0][0]); o[0][1] = ffma2(a0.x, bh, o[0][1]);
                          o[1][0] = ffma2(a1.x, bl, o[1][0]); o[1][1] = ffma2(a1.x, bh, o[1][1]);
                          o[2][0] = ffma2(a2.x, bl, o[2][0]); o[2][1] = ffma2(a2.x, bh, o[2][1]);
                          o[3][0] = ffma2(a3.x, bl, o[3][0]); o[3][1] = ffma2(a3.x, bh, o[3][1]); }
                        unpack2(wv1, wl, wh);
                        { ULL bl = pack2(wl), bh = pack2(wh);
                          o[0][0] = ffma2(a0.y, bl, o[0][0]); o[0][1] = ffma2(a0.y, bh, o[0][1]);
                          o[1][0] = ffma2(a1.y, bl, o[1][0]); o[1][1] = ffma2(a1.y, bh, o[1][1]);
                          o[2][0] = ffma2(a2.y, bl, o[2][0]); o[2][1] = ffma2(a2.y, bh, o[2][1]);
                          o[3][0] = ffma2(a3.y, bl, o[3][0]); o[3][1] = ffma2(a3.y, bh, o[3][1]); }
                    }
                }
            }

            // ------- partner reduction: group1 -> Red, group0 adds ----------
            if (gr == 1) {
                ULL* rd = &Red[((w - 8) * 32 + tc) * 8];
                #pragma unroll
                for (int p = 0; p < 4; p++) {
                    ulonglong2 v; v.x = o[p][0]; v.y = o[p][1];
                    *(ulonglong2*)&rd[2 * p] = v;
                }
            }
            __syncthreads();
            if (gr == 0) {
                const ULL* rd = &Red[(w * 32 + tc) * 8];
                const ULL ONE = pack2(1.0f);
                #pragma unroll
                for (int p = 0; p < 4; p++) {
                    ulonglong2 v = *(const ulonglong2*)&rd[2 * p];
                    o[p][0] = ffma2(ONE, v.x, o[p][0]);
                    o[p][1] = ffma2(ONE, v.y, o[p][1]);
                }
            }

            // ---------------- RK4 epilogue (packed, warps 0-7) --------------
            if (epi_w) {
                if (s == 0) {
                    #pragma unroll
                    for (int p = 0; p < 4; p++) { acc[p][0] = o[p][0]; acc[p][1] = o[p][1]; }
                } else {
                    ULL cwv = pack2((s == 3) ? 1.0f : 2.0f);
                    #pragma unroll
                    for (int p = 0; p < 4; p++) {
                        acc[p][0] = ffma2(cwv, o[p][0], acc[p][0]);
                        acc[p][1] = ffma2(cwv, o[p][1], acc[p][1]);
                    }
                }
                if (s < 3) {
                    ULL ewv = pack2((s < 2) ? half : dt);
                    #pragma unroll
                    for (int p = 0; p < 4; p++) {
                        ulonglong2 yy;
                        yy.x = ffma2(ewv, o[p][0], yb[p][0]);
                        yy.y = ffma2(ewv, o[p][1], yb[p][1]);
                        *(ulonglong2*)&Yp[(4 * rg + p) * LATENTS + cb] = yy;
                    }
                } else {
                    ULL c6 = pack2(dt * (1.0f / 6.0f));
                    #pragma unroll
                    for (int p = 0; p < 4; p++) {
                        yb[p][0] = ffma2(c6, acc[p][0], yb[p][0]);
                        yb[p][1] = ffma2(c6, acc[p][1], yb[p][1]);
                        ulonglong2 yy; yy.x = yb[p][0]; yy.y = yb[p][1];
                        *(ulonglong2*)&Yp[(4 * rg + p) * LATENTS + cb] = yy;
                        int r = row0 + 8 * rg + 2 * p;
                        float lo, hi;
                        size_t base0 = ((size_t)r * TSTEPS + (t + 1)) * LATENTS + cb;
                        size_t base1 = ((size_t)(r + 1) * TSTEPS + (t + 1)) * LATENTS + cb;
                        unpack2(yb[p][0], lo, hi);
                        out[base0] = lo;     out[base1] = hi;
                        unpack2(yb[p][1], lo, hi);
                        out[base0 + 1] = lo; out[base1 + 1] = hi;
                    }
                }
            }
            __syncthreads();
        }
    }
}

extern "C" void kernel_launch(void* const* d_in, const int* in_sizes, int n_in,
                              void* d_out, int out_size) {
    const float* fp = (const float*)d_in[0];
    const float* ts = (const float*)d_in[1];
    const float* W1 = (const float*)d_in[2];
    const float* b1 = (const float*)d_in[3];
    const float* W2 = (const float*)d_in[4];
    const float* b2 = (const float*)d_in[5];
    float* out = (float*)d_out;

    cudaFuncSetAttribute(ode_rk4_kernel,
                         cudaFuncAttributeMaxDynamicSharedMemorySize, SM_BYTES);
    ode_rk4_kernel<<<NROWS / TM, NTHR, SM_BYTES>>>(fp, ts, W1, b1, W2, b2, out);
}